// round 1
// baseline (speedup 1.0000x reference)
#include <cuda_runtime.h>
#include <cstdint>

// Problem constants
#define TT   8
#define BB   16
#define NTOK 197
#define CD   768
#define BTOT 128           // B*T
#define OC3  2304          // 3*C
#define NCOLS 25216        // BTOT*NTOK, flattened column dim per g
#define OUTBT 453888       // OC3*NTOK

// Scales s[bt, 3C]  (bt*2304 + oc)
__device__ float g_s[BTOT * OC3];

__device__ __forceinline__ unsigned f2tf(float f) {
    unsigned r;
    asm("cvt.rna.tf32.f32 %0, %1;" : "=r"(r) : "f"(f));
    return r;
}

// ---------------------------------------------------------------------------
// Routing: r[b,oc,t] = conv1d_k3(cls)[oc,t] + ab[oc] + 1  -> g_s[(b*8+t)*2304+oc]
// block = (b, 32-oc chunk); 256 threads = 32 oc x 8 t
// ---------------------------------------------------------------------------
__global__ __launch_bounds__(256) void routing_kernel(
    const float* __restrict__ x, const float* __restrict__ aw,
    const float* __restrict__ ab)
{
    __shared__ float cls[10][772];   // rows 1..8 = cls tokens, 0/9 zero pad; stride 772 avoids conflicts
    const int b   = blockIdx.x;
    const int oc0 = blockIdx.y * 32;
    const int tid = threadIdx.x;

    #pragma unroll
    for (int tp = 0; tp < 8; tp++)
        for (int ic = tid; ic < 768; ic += 256)
            cls[tp + 1][ic] = x[(size_t)((b * 8 + tp) * 197) * 768 + ic];
    for (int ic = tid; ic < 772; ic += 256) { cls[0][ic] = 0.f; cls[9][ic] = 0.f; }
    __syncthreads();

    const int ocl = tid >> 3;
    const int t   = tid & 7;
    const int oc  = oc0 + ocl;
    const float* wr = aw + (size_t)oc * 2304;   // aw[oc, ic, k], k fastest

    float acc = 0.f;
    #pragma unroll 4
    for (int ic = 0; ic < 768; ic += 4) {
        float4 w0 = *(const float4*)(wr + ic * 3);
        float4 w1 = *(const float4*)(wr + ic * 3 + 4);
        float4 w2 = *(const float4*)(wr + ic * 3 + 8);
        float4 c0 = *(const float4*)&cls[t    ][ic];
        float4 c1 = *(const float4*)&cls[t + 1][ic];
        float4 c2 = *(const float4*)&cls[t + 2][ic];
        acc += c0.x * w0.x + c1.x * w0.y + c2.x * w0.z;
        acc += c0.y * w0.w + c1.y * w1.x + c2.y * w1.y;
        acc += c0.z * w1.z + c1.z * w1.w + c2.z * w2.x;
        acc += c0.w * w2.y + c1.w * w2.z + c2.w * w2.w;
    }
    g_s[(b * 8 + t) * 2304 + oc] = acc + ab[oc] + 1.0f;
}

// ---------------------------------------------------------------------------
// Main GEMM: per g, out[o, cj] = sum_i W[g,o,i]*s[bt(cj),g,i]*x[cj,i]
//   M = 768 (o), N = 25216 (cj = bt*197 + n), K = 768
// tf32 mma.sync m16n8k8, block tile 128x128, K-chunk 16, double-buffered smem
// grid = (18 = g*6+mtile  [fastest -> x-tile L2 reuse], 197 = ntile)
// ---------------------------------------------------------------------------
#define KC   16
#define STR  20          // smem row stride (floats): conflict-free for frag LDS
#define NKCH 48          // 768/16

__global__ __launch_bounds__(256) void tal_main_kernel(
    const float* __restrict__ x, const float* __restrict__ w,
    const float* __restrict__ bias, float* __restrict__ out)
{
    __shared__ __align__(16) unsigned As[2][128 * STR];
    __shared__ __align__(16) unsigned Bs[2][128 * STR];

    const int bx   = blockIdx.x;          // 0..17
    const int g    = bx / 6, mt = bx % 6;
    const int col0 = blockIdx.y * 128;    // base flattened column
    const int tid  = threadIdx.x;
    const int lane = tid & 31, warp = tid >> 5;
    const int wm = warp & 3, wn = warp >> 2;   // 4x2 warp grid (32x64 warp tile)
    const int lr = lane >> 2, lc = lane & 3;

    const float* wbase = w + (size_t)(g * 768 + mt * 128) * 768;

    // gmem staging: each thread owns two float4s of the 128x16 chunk
    const int r0  = tid >> 2;            // 0..63
    const int r1  = r0 + 64;             // 64..127
    const int kq  = (tid & 3) * 4;       // k offset within chunk

    const int bc0 = col0 + r0, bc1 = col0 + r1;
    const int bt0 = bc0 / 197, bt1 = bc1 / 197;
    const float* xr0 = x + (size_t)bc0 * 768;
    const float* xr1 = x + (size_t)bc1 * 768;
    const float* sr0 = g_s + bt0 * 2304 + g * 768;
    const float* sr1 = g_s + bt1 * 2304 + g * 768;

    float4 aR0, aR1, xR0, xR1, sR0, sR1;

    auto LDG = [&](int kb) {
        aR0 = *(const float4*)(wbase + (size_t)r0 * 768 + kb + kq);
        aR1 = *(const float4*)(wbase + (size_t)r1 * 768 + kb + kq);
        xR0 = *(const float4*)(xr0 + kb + kq);
        xR1 = *(const float4*)(xr1 + kb + kq);
        sR0 = *(const float4*)(sr0 + kb + kq);
        sR1 = *(const float4*)(sr1 + kb + kq);
    };
    auto STS = [&](int buf) {
        uint4 a0 = { f2tf(aR0.x), f2tf(aR0.y), f2tf(aR0.z), f2tf(aR0.w) };
        uint4 a1 = { f2tf(aR1.x), f2tf(aR1.y), f2tf(aR1.z), f2tf(aR1.w) };
        uint4 b0 = { f2tf(xR0.x * sR0.x), f2tf(xR0.y * sR0.y),
                     f2tf(xR0.z * sR0.z), f2tf(xR0.w * sR0.w) };
        uint4 b1 = { f2tf(xR1.x * sR1.x), f2tf(xR1.y * sR1.y),
                     f2tf(xR1.z * sR1.z), f2tf(xR1.w * sR1.w) };
        *(uint4*)&As[buf][r0 * STR + kq] = a0;
        *(uint4*)&As[buf][r1 * STR + kq] = a1;
        *(uint4*)&Bs[buf][r0 * STR + kq] = b0;
        *(uint4*)&Bs[buf][r1 * STR + kq] = b1;
    };

    float acc[2][8][4];
    #pragma unroll
    for (int mi = 0; mi < 2; mi++)
        #pragma unroll
        for (int ni = 0; ni < 8; ni++)
            #pragma unroll
            for (int e = 0; e < 4; e++) acc[mi][ni][e] = 0.f;

    LDG(0);
    STS(0);
    __syncthreads();

    int buf = 0;
    for (int c = 0; c < NKCH; c++) {
        if (c + 1 < NKCH) LDG((c + 1) * KC);

        #pragma unroll
        for (int ks = 0; ks < 2; ks++) {
            const int k0 = ks * 8;
            unsigned af[2][4];
            #pragma unroll
            for (int mi = 0; mi < 2; mi++) {
                int rb = wm * 32 + mi * 16;
                af[mi][0] = As[buf][(rb + lr)     * STR + k0 + lc];
                af[mi][1] = As[buf][(rb + 8 + lr) * STR + k0 + lc];
                af[mi][2] = As[buf][(rb + lr)     * STR + k0 + 4 + lc];
                af[mi][3] = As[buf][(rb + 8 + lr) * STR + k0 + 4 + lc];
            }
            unsigned bfr[8][2];
            #pragma unroll
            for (int ni = 0; ni < 8; ni++) {
                int cb = wn * 64 + ni * 8;
                bfr[ni][0] = Bs[buf][(cb + lr) * STR + k0 + lc];
                bfr[ni][1] = Bs[buf][(cb + lr) * STR + k0 + 4 + lc];
            }
            #pragma unroll
            for (int mi = 0; mi < 2; mi++)
                #pragma unroll
                for (int ni = 0; ni < 8; ni++)
                    asm volatile(
                        "mma.sync.aligned.m16n8k8.row.col.f32.tf32.tf32.f32 "
                        "{%0,%1,%2,%3},{%4,%5,%6,%7},{%8,%9},{%0,%1,%2,%3};\n"
                        : "+f"(acc[mi][ni][0]), "+f"(acc[mi][ni][1]),
                          "+f"(acc[mi][ni][2]), "+f"(acc[mi][ni][3])
                        : "r"(af[mi][0]), "r"(af[mi][1]),
                          "r"(af[mi][2]), "r"(af[mi][3]),
                          "r"(bfr[ni][0]), "r"(bfr[ni][1]));
        }

        if (c + 1 < NKCH) STS(buf ^ 1);
        __syncthreads();
        buf ^= 1;
    }

    // Epilogue: out[bt, g*768+o, n] = acc + bias[oc]*s[bt, oc]
    #pragma unroll
    for (int mi = 0; mi < 2; mi++) {
        #pragma unroll
        for (int ni = 0; ni < 8; ni++) {
            #pragma unroll
            for (int e = 0; e < 4; e++) {
                int ocl = mt * 128 + wm * 32 + mi * 16 + lr + ((e & 2) ? 8 : 0);
                int col = col0 + wn * 64 + ni * 8 + lc * 2 + (e & 1);
                int oc  = g * 768 + ocl;
                int bt  = col / 197;
                int n   = col - bt * 197;
                float v = acc[mi][ni][e] + bias[oc] * g_s[bt * 2304 + oc];
                out[(size_t)bt * OUTBT + (size_t)oc * 197 + n] = v;
            }
        }
    }
}

extern "C" void kernel_launch(void* const* d_in, const int* in_sizes, int n_in,
                              void* d_out, int out_size)
{
    const float* x    = (const float*)d_in[0];
    const float* aw   = (const float*)d_in[1];
    const float* ab   = (const float*)d_in[2];
    const float* w    = (const float*)d_in[3];
    const float* bias = (const float*)d_in[4];
    float* out = (float*)d_out;

    routing_kernel<<<dim3(16, 72), 256>>>(x, aw, ab);
    tal_main_kernel<<<dim3(18, 197), 256>>>(x, w, bias, out);
}

// round 3
// speedup vs baseline: 1.7470x; 1.7470x over previous
#include <cuda_runtime.h>
#include <cstdint>

// ---------------- problem constants ----------------
#define NTOK  197
#define BTOT  128          // B*T
#define OC3   2304         // 3*C
#define NCOLS 25216        // BTOT*NTOK
#define OUTBT 453888       // OC3*NTOK

// ---------------- device scratch (static globals: allowed) ----------------
__device__ float    g_s[BTOT * OC3];            // routing scales, 1.18 MB
__device__ unsigned g_wt[OC3 * 768];            // tf32(W), 7.1 MB
__device__ unsigned g_xs[3][NCOLS * 768];       // tf32(x*s) per group, 232 MB

// ---------------- helpers ----------------
__device__ __forceinline__ uint32_t smem_u32(const void* p) {
    uint32_t a;
    asm("{ .reg .u64 t; cvta.to.shared.u64 t, %1; cvt.u32.u64 %0, t; }" : "=r"(a) : "l"(p));
    return a;
}
__device__ __forceinline__ unsigned f2tf(float f) {
    unsigned r;
    asm("cvt.rna.tf32.f32 %0, %1;" : "=r"(r) : "f"(f));
    return r;
}
__device__ __forceinline__ void cp_async16(uint32_t dst, const void* src) {
    asm volatile("cp.async.cg.shared.global [%0], [%1], 16;" :: "r"(dst), "l"(src) : "memory");
}
#define CP_COMMIT() asm volatile("cp.async.commit_group;" ::: "memory")
#define CP_WAIT1()  asm volatile("cp.async.wait_group 1;" ::: "memory")

#define LDSM_X4(r0, r1, r2, r3, addr) \
    asm volatile("ldmatrix.sync.aligned.m8n8.x4.shared.b16 {%0,%1,%2,%3}, [%4];" \
        : "=r"(r0), "=r"(r1), "=r"(r2), "=r"(r3) : "r"(addr))

#define SWZ(off) ((off) ^ (((off) >> 3) & 0x70))

// ---------------------------------------------------------------------------
// Routing: r[b,oc,t] = conv1d_k3(cls)[oc,t] + ab[oc] + 1 -> g_s[(b*8+t)*2304+oc]
// One thread per oc handles ALL 8 t (weights read once). grid=(16,9), block 256.
// ---------------------------------------------------------------------------
__global__ __launch_bounds__(256) void routing_kernel(
    const float* __restrict__ x, const float* __restrict__ aw,
    const float* __restrict__ ab)
{
    __shared__ float cls[10][772];   // rows 1..8 = cls(t), 0/9 zero pad
    const int b   = blockIdx.x;
    const int oc  = blockIdx.y * 256 + threadIdx.x;
    const int tid = threadIdx.x;

    #pragma unroll
    for (int tp = 0; tp < 8; tp++)
        for (int ic = tid; ic < 768; ic += 256)
            cls[tp + 1][ic] = x[(size_t)((b * 8 + tp) * 197) * 768 + ic];
    for (int ic = tid; ic < 772; ic += 256) { cls[0][ic] = 0.f; cls[9][ic] = 0.f; }
    __syncthreads();

    const float* wr = aw + (size_t)oc * 2304;   // aw[oc][ic][k]
    float acc[8];
    #pragma unroll
    for (int t = 0; t < 8; t++) acc[t] = 0.f;

    for (int ic = 0; ic < 768; ic += 4) {
        float4 w0 = *(const float4*)(wr + ic * 3);
        float4 w1 = *(const float4*)(wr + ic * 3 + 4);
        float4 w2 = *(const float4*)(wr + ic * 3 + 8);
        float cv[10][4];
        #pragma unroll
        for (int j = 0; j < 10; j++) {
            cv[j][0] = cls[j][ic];     cv[j][1] = cls[j][ic + 1];
            cv[j][2] = cls[j][ic + 2]; cv[j][3] = cls[j][ic + 3];
        }
        #pragma unroll
        for (int t = 0; t < 8; t++) {
            acc[t] += cv[t][0] * w0.x + cv[t+1][0] * w0.y + cv[t+2][0] * w0.z;
            acc[t] += cv[t][1] * w0.w + cv[t+1][1] * w1.x + cv[t+2][1] * w1.y;
            acc[t] += cv[t][2] * w1.z + cv[t+1][2] * w1.w + cv[t+2][2] * w2.x;
            acc[t] += cv[t][3] * w2.y + cv[t+1][3] * w2.z + cv[t+2][3] * w2.w;
        }
    }
    float abv = ab[oc] + 1.0f;
    #pragma unroll
    for (int t = 0; t < 8; t++)
        g_s[(b * 8 + t) * 2304 + oc] = acc[t] + abv;
}

// ---------------------------------------------------------------------------
// Prep: W -> tf32(RNA) ;  x,s -> tf32(x*s) per group
// ---------------------------------------------------------------------------
__global__ __launch_bounds__(256) void prep_w(const float* __restrict__ w)
{
    int i = (blockIdx.x * 256 + threadIdx.x) * 4;
    float4 v = *(const float4*)(w + i);
    uint4 o = { f2tf(v.x), f2tf(v.y), f2tf(v.z), f2tf(v.w) };
    *(uint4*)(g_wt + i) = o;
}

__global__ __launch_bounds__(192) void prep_xs(const float* __restrict__ x)
{
    const int col = blockIdx.x;
    const int k   = threadIdx.x * 4;
    const int bt  = col / 197;
    float4 xv = *(const float4*)(x + (size_t)col * 768 + k);
    #pragma unroll
    for (int g = 0; g < 3; g++) {
        float4 sv = *(const float4*)(g_s + bt * 2304 + g * 768 + k);
        uint4 o = { f2tf(xv.x * sv.x), f2tf(xv.y * sv.y),
                    f2tf(xv.z * sv.z), f2tf(xv.w * sv.w) };
        *(uint4*)(&g_xs[g][(size_t)col * 768 + k]) = o;
    }
}

// ---------------------------------------------------------------------------
// Main GEMM (mma.sync tf32 m16n8k8): per g, out[o,cj] = sum_k Wt[o,k]*Xs[cj,k]
// CTA tile 128x128, BK=32, 3-stage cp.async, ldmatrix fragments.
// 8 warps = 2(m) x 4(n): warp tile 64x32. grid=(18, 197), block 256.
// ---------------------------------------------------------------------------
#define STAGES      3
#define STAGE_BYTES 32768            // A 16K + B 16K
#define SMEM_MAIN   (STAGES * STAGE_BYTES)

__global__ __launch_bounds__(256, 2)
void tal_main_kernel(const float* __restrict__ bias, float* __restrict__ out)
{
    extern __shared__ char smem[];
    const uint32_t sb = smem_u32(smem);

    const int bx   = blockIdx.x;
    const int g    = bx / 6, mt = bx % 6;
    const int col0 = blockIdx.y * 128;
    const int tid  = threadIdx.x;
    const int lane = tid & 31, warp = tid >> 5;
    const int wm = warp & 1, wn = warp >> 1;      // 2x4 warp grid, 64x32 tiles
    const int lr = lane >> 2, lc = lane & 3;

    // ---- cp.async slot setup: 4 x 16B per operand per thread per chunk ----
    uint32_t dsto[4];
    const unsigned* asrc[4];
    const unsigned* bsrc[4];
    #pragma unroll
    for (int i = 0; i < 4; i++) {
        int idx = tid + i * 256;
        int row = idx >> 3;
        int q   = idx & 7;
        uint32_t off = (uint32_t)(row * 128 + q * 16);
        dsto[i] = SWZ(off);
        asrc[i] = g_wt + (size_t)(g * 768 + mt * 128 + row) * 768 + q * 4;
        bsrc[i] = g_xs[g] + (size_t)(col0 + row) * 768 + q * 4;
    }

    // ---- ldmatrix base offsets (ks=0); per-ks addr = base + (off ^ (ks<<5)) ----
    const int lrow = lane & 15, qhi = lane >> 4;
    uint32_t aoff[4], boff[2];
    #pragma unroll
    for (int mi = 0; mi < 4; mi++) {
        uint32_t off = (uint32_t)((wm * 64 + mi * 16 + lrow) * 128 + qhi * 16);
        aoff[mi] = SWZ(off);
    }
    #pragma unroll
    for (int nj = 0; nj < 2; nj++) {
        uint32_t off = (uint32_t)((wn * 32 + nj * 16 + lrow) * 128 + qhi * 16);
        boff[nj] = SWZ(off);
    }

    float acc[4][4][4];
    #pragma unroll
    for (int mi = 0; mi < 4; mi++)
        #pragma unroll
        for (int ni = 0; ni < 4; ni++)
            #pragma unroll
            for (int e = 0; e < 4; e++) acc[mi][ni][e] = 0.f;

    auto COPY = [&](int st, int c) {
        uint32_t sA = sb + st * STAGE_BYTES;
        uint32_t sB = sA + 16384;
        #pragma unroll
        for (int i = 0; i < 4; i++) {
            cp_async16(sA + dsto[i], asrc[i] + c * 32);
            cp_async16(sB + dsto[i], bsrc[i] + c * 32);
        }
    };

    COPY(0, 0); CP_COMMIT();
    COPY(1, 1); CP_COMMIT();

    int st = 0, pf = 2;
    for (int c = 0; c < 24; c++) {
        CP_WAIT1();
        __syncthreads();
        if (c + 2 < 24) COPY(pf, c + 2);
        CP_COMMIT();

        const uint32_t sA = sb + st * STAGE_BYTES;
        const uint32_t sB = sA + 16384;
        #pragma unroll
        for (int ks = 0; ks < 4; ks++) {
            const uint32_t kx = (uint32_t)(ks << 5);
            uint32_t a[4][4], b[2][4];
            #pragma unroll
            for (int mi = 0; mi < 4; mi++)
                LDSM_X4(a[mi][0], a[mi][1], a[mi][2], a[mi][3], sA + (aoff[mi] ^ kx));
            #pragma unroll
            for (int nj = 0; nj < 2; nj++)
                LDSM_X4(b[nj][0], b[nj][1], b[nj][2], b[nj][3], sB + (boff[nj] ^ kx));
            #pragma unroll
            for (int mi = 0; mi < 4; mi++)
                #pragma unroll
                for (int ni = 0; ni < 4; ni++) {
                    const uint32_t b0 = b[ni >> 1][ni & 1];
                    const uint32_t b1 = b[ni >> 1][(ni & 1) + 2];
                    asm volatile(
                        "mma.sync.aligned.m16n8k8.row.col.f32.tf32.tf32.f32 "
                        "{%0,%1,%2,%3},{%4,%5,%6,%7},{%8,%9},{%0,%1,%2,%3};\n"
                        : "+f"(acc[mi][ni][0]), "+f"(acc[mi][ni][1]),
                          "+f"(acc[mi][ni][2]), "+f"(acc[mi][ni][3])
                        : "r"(a[mi][0]), "r"(a[mi][1]), "r"(a[mi][2]), "r"(a[mi][3]),
                          "r"(b0), "r"(b1));
                }
        }
        st = (st + 1 == 3) ? 0 : st + 1;
        pf = (pf + 1 == 3) ? 0 : pf + 1;
    }

    // ---- epilogue: out[bt, oc, n] = acc + bias[oc]*s[bt,oc] ----
    const int bt_base = col0 / 197;
    const int col197  = (bt_base + 1) * 197;
    int bt1 = bt_base + 1; if (bt1 > 127) bt1 = 127;

    float bvsv[4][2][2];
    #pragma unroll
    for (int mi = 0; mi < 4; mi++)
        #pragma unroll
        for (int h = 0; h < 2; h++) {
            int oc = g * 768 + mt * 128 + wm * 64 + mi * 16 + lr + h * 8;
            float bv = bias[oc];
            bvsv[mi][h][0] = bv * g_s[bt_base * 2304 + oc];
            bvsv[mi][h][1] = bv * g_s[bt1 * 2304 + oc];
        }

    #pragma unroll
    for (int mi = 0; mi < 4; mi++)
        #pragma unroll
        for (int ni = 0; ni < 4; ni++)
            #pragma unroll
            for (int e = 0; e < 4; e++) {
                const int h   = e >> 1;
                const int oc  = g * 768 + mt * 128 + wm * 64 + mi * 16 + lr + h * 8;
                const int col = col0 + wn * 32 + ni * 8 + lc * 2 + (e & 1);
                const int bs  = (col >= col197) ? 1 : 0;
                const float add = bs ? bvsv[mi][h][1] : bvsv[mi][h][0];
                // idx = bt*OUTBT + oc*197 + (col - bt*197) = col + oc*197 + bt*453691
                const size_t idx = (size_t)col + (size_t)oc * 197
                                 + (size_t)(bt_base + bs) * 453691;
                out[idx] = acc[mi][ni][e] + add;
            }
}

extern "C" void kernel_launch(void* const* d_in, const int* in_sizes, int n_in,
                              void* d_out, int out_size)
{
    const float* x    = (const float*)d_in[0];
    const float* aw   = (const float*)d_in[1];
    const float* ab   = (const float*)d_in[2];
    const float* w    = (const float*)d_in[3];
    const float* bias = (const float*)d_in[4];
    float* out = (float*)d_out;

    cudaFuncSetAttribute(tal_main_kernel,
                         cudaFuncAttributeMaxDynamicSharedMemorySize, SMEM_MAIN);

    routing_kernel<<<dim3(16, 9), 256>>>(x, aw, ab);
    prep_w<<<OC3 * 768 / 1024, 256>>>(w);
    prep_xs<<<NCOLS, 192>>>(x);
    tal_main_kernel<<<dim3(18, 197), 256, SMEM_MAIN>>>(bias, out);
}

// round 4
// speedup vs baseline: 1.7582x; 1.0064x over previous
#include <cuda_runtime.h>
#include <cstdint>

// ---------------- problem constants ----------------
#define NTOK  197
#define BTOT  128          // B*T
#define OC3   2304         // 3*C
#define NCOLS 25216        // BTOT*NTOK
#define OUTBT 453888       // OC3*NTOK

// ---------------- device scratch (static globals: allowed) ----------------
__device__ float    g_s[BTOT * OC3];            // routing scales, 1.18 MB
__device__ unsigned g_wt[OC3 * 768];            // tf32(W), 7.1 MB
__device__ unsigned g_xs[3][NCOLS * 768];       // tf32(x*s) per group, 232 MB

// ---------------- helpers ----------------
__device__ __forceinline__ uint32_t smem_u32(const void* p) {
    uint32_t a;
    asm("{ .reg .u64 t; cvta.to.shared.u64 t, %1; cvt.u32.u64 %0, t; }" : "=r"(a) : "l"(p));
    return a;
}
__device__ __forceinline__ unsigned f2tf(float f) {
    unsigned r;
    asm("cvt.rna.tf32.f32 %0, %1;" : "=r"(r) : "f"(f));
    return r;
}
__device__ __forceinline__ void cp_async16(uint32_t dst, const void* src) {
    asm volatile("cp.async.cg.shared.global [%0], [%1], 16;" :: "r"(dst), "l"(src) : "memory");
}
#define CP_COMMIT() asm volatile("cp.async.commit_group;" ::: "memory")
#define CP_WAIT1()  asm volatile("cp.async.wait_group 1;" ::: "memory")

#define LDSM_X4(r0, r1, r2, r3, addr) \
    asm volatile("ldmatrix.sync.aligned.m8n8.x4.shared.b16 {%0,%1,%2,%3}, [%4];" \
        : "=r"(r0), "=r"(r1), "=r"(r2), "=r"(r3) : "r"(addr))

#define SWZ(off) ((off) ^ (((off) >> 3) & 0x70))

// ---------------------------------------------------------------------------
// Routing: r[b,oc,t] = conv1d_k3(cls)[oc,t] + ab[oc] + 1 -> g_s[(b*8+t)*2304+oc]
// One thread per oc handles ALL 8 t (weights read once). grid=(16,9), block 256.
// ---------------------------------------------------------------------------
__global__ __launch_bounds__(256) void routing_kernel(
    const float* __restrict__ x, const float* __restrict__ aw,
    const float* __restrict__ ab)
{
    __shared__ float cls[10][772];   // rows 1..8 = cls(t), 0/9 zero pad
    const int b   = blockIdx.x;
    const int oc  = blockIdx.y * 256 + threadIdx.x;
    const int tid = threadIdx.x;

    #pragma unroll
    for (int tp = 0; tp < 8; tp++)
        for (int ic = tid; ic < 768; ic += 256)
            cls[tp + 1][ic] = x[(size_t)((b * 8 + tp) * 197) * 768 + ic];
    for (int ic = tid; ic < 772; ic += 256) { cls[0][ic] = 0.f; cls[9][ic] = 0.f; }
    __syncthreads();

    const float* wr = aw + (size_t)oc * 2304;   // aw[oc][ic][k]
    float acc[8];
    #pragma unroll
    for (int t = 0; t < 8; t++) acc[t] = 0.f;

    for (int ic = 0; ic < 768; ic += 4) {
        float4 w0 = *(const float4*)(wr + ic * 3);
        float4 w1 = *(const float4*)(wr + ic * 3 + 4);
        float4 w2 = *(const float4*)(wr + ic * 3 + 8);
        float cv[10][4];
        #pragma unroll
        for (int j = 0; j < 10; j++) {
            cv[j][0] = cls[j][ic];     cv[j][1] = cls[j][ic + 1];
            cv[j][2] = cls[j][ic + 2]; cv[j][3] = cls[j][ic + 3];
        }
        #pragma unroll
        for (int t = 0; t < 8; t++) {
            acc[t] += cv[t][0] * w0.x + cv[t+1][0] * w0.y + cv[t+2][0] * w0.z;
            acc[t] += cv[t][1] * w0.w + cv[t+1][1] * w1.x + cv[t+2][1] * w1.y;
            acc[t] += cv[t][2] * w1.z + cv[t+1][2] * w1.w + cv[t+2][2] * w2.x;
            acc[t] += cv[t][3] * w2.y + cv[t+1][3] * w2.z + cv[t+2][3] * w2.w;
        }
    }
    float abv = ab[oc] + 1.0f;
    #pragma unroll
    for (int t = 0; t < 8; t++)
        g_s[(b * 8 + t) * 2304 + oc] = acc[t] + abv;
}

// ---------------------------------------------------------------------------
// Prep: W -> tf32(RNA) ;  x,s -> tf32(x*s) per group
// ---------------------------------------------------------------------------
__global__ __launch_bounds__(256) void prep_w(const float* __restrict__ w)
{
    int i = (blockIdx.x * 256 + threadIdx.x) * 4;
    float4 v = *(const float4*)(w + i);
    uint4 o = { f2tf(v.x), f2tf(v.y), f2tf(v.z), f2tf(v.w) };
    *(uint4*)(g_wt + i) = o;
}

__global__ __launch_bounds__(192) void prep_xs(const float* __restrict__ x)
{
    const int col = blockIdx.x;
    const int k   = threadIdx.x * 4;
    const int bt  = col / 197;
    float4 xv = *(const float4*)(x + (size_t)col * 768 + k);
    #pragma unroll
    for (int g = 0; g < 3; g++) {
        float4 sv = *(const float4*)(g_s + bt * 2304 + g * 768 + k);
        uint4 o = { f2tf(xv.x * sv.x), f2tf(xv.y * sv.y),
                    f2tf(xv.z * sv.z), f2tf(xv.w * sv.w) };
        *(uint4*)(&g_xs[g][(size_t)col * 768 + k]) = o;
    }
}

// ---------------------------------------------------------------------------
// Main GEMM (mma.sync tf32 m16n8k8): per g, out[o,cj] = sum_k Wt[o,k]*Xs[cj,k]
// CTA tile 128x128, BK=32, 3-stage cp.async, ldmatrix fragments.
// 4 warps = 2(m) x 2(n): warp tile 64x64 (LDS/MMA = 128B). 2 CTAs/SM.
// grid = (18, 197), block 128.
// ---------------------------------------------------------------------------
#define STAGES      3
#define STAGE_BYTES 32768            // A 16K + B 16K
#define SMEM_MAIN   (STAGES * STAGE_BYTES)

__global__ __launch_bounds__(128, 2)
void tal_main_kernel(const float* __restrict__ bias, float* __restrict__ out)
{
    extern __shared__ char smem[];
    const uint32_t sb = smem_u32(smem);

    const int bx   = blockIdx.x;
    const int g    = bx / 6, mt = bx % 6;
    const int col0 = blockIdx.y * 128;
    const int tid  = threadIdx.x;
    const int lane = tid & 31, warp = tid >> 5;
    const int wm = warp & 1, wn = warp >> 1;      // 2x2 warp grid, 64x64 tiles
    const int lr = lane >> 2, lc = lane & 3;

    // ---- cp.async slot setup: 8 x 16B per operand per thread per chunk ----
    uint32_t dsto[8];
    const unsigned* asrc[8];
    const unsigned* bsrc[8];
    #pragma unroll
    for (int i = 0; i < 8; i++) {
        int idx = tid + i * 128;
        int row = idx >> 3;
        int q   = idx & 7;
        uint32_t off = (uint32_t)(row * 128 + q * 16);
        dsto[i] = SWZ(off);
        asrc[i] = g_wt + (size_t)(g * 768 + mt * 128 + row) * 768 + q * 4;
        bsrc[i] = g_xs[g] + (size_t)(col0 + row) * 768 + q * 4;
    }

    // ---- ldmatrix base offsets (ks=0); per-ks addr = base + (off ^ (ks<<5)) ----
    const int lrow = lane & 15, qhi = lane >> 4;
    uint32_t aoff[4], boff[4];
    #pragma unroll
    for (int mi = 0; mi < 4; mi++) {
        uint32_t off = (uint32_t)((wm * 64 + mi * 16 + lrow) * 128 + qhi * 16);
        aoff[mi] = SWZ(off);
    }
    #pragma unroll
    for (int nj = 0; nj < 4; nj++) {
        uint32_t off = (uint32_t)((wn * 64 + nj * 16 + lrow) * 128 + qhi * 16);
        boff[nj] = SWZ(off);
    }

    float acc[4][8][4];
    #pragma unroll
    for (int mi = 0; mi < 4; mi++)
        #pragma unroll
        for (int ni = 0; ni < 8; ni++)
            #pragma unroll
            for (int e = 0; e < 4; e++) acc[mi][ni][e] = 0.f;

    auto COPY = [&](int st, int c) {
        uint32_t sA = sb + st * STAGE_BYTES;
        uint32_t sB = sA + 16384;
        #pragma unroll
        for (int i = 0; i < 8; i++) {
            cp_async16(sA + dsto[i], asrc[i] + c * 32);
            cp_async16(sB + dsto[i], bsrc[i] + c * 32);
        }
    };

    COPY(0, 0); CP_COMMIT();
    COPY(1, 1); CP_COMMIT();

    int st = 0, pf = 2;
    for (int c = 0; c < 24; c++) {
        CP_WAIT1();
        __syncthreads();
        if (c + 2 < 24) COPY(pf, c + 2);
        CP_COMMIT();

        const uint32_t sA = sb + st * STAGE_BYTES;
        const uint32_t sB = sA + 16384;
        #pragma unroll
        for (int ks = 0; ks < 4; ks++) {
            const uint32_t kx = (uint32_t)(ks << 5);
            uint32_t a[4][4], b[4][4];
            #pragma unroll
            for (int mi = 0; mi < 4; mi++)
                LDSM_X4(a[mi][0], a[mi][1], a[mi][2], a[mi][3], sA + (aoff[mi] ^ kx));
            #pragma unroll
            for (int nj = 0; nj < 4; nj++)
                LDSM_X4(b[nj][0], b[nj][1], b[nj][2], b[nj][3], sB + (boff[nj] ^ kx));
            #pragma unroll
            for (int mi = 0; mi < 4; mi++)
                #pragma unroll
                for (int ni = 0; ni < 8; ni++) {
                    const uint32_t b0 = b[ni >> 1][ni & 1];
                    const uint32_t b1 = b[ni >> 1][(ni & 1) + 2];
                    asm volatile(
                        "mma.sync.aligned.m16n8k8.row.col.f32.tf32.tf32.f32 "
                        "{%0,%1,%2,%3},{%4,%5,%6,%7},{%8,%9},{%0,%1,%2,%3};\n"
                        : "+f"(acc[mi][ni][0]), "+f"(acc[mi][ni][1]),
                          "+f"(acc[mi][ni][2]), "+f"(acc[mi][ni][3])
                        : "r"(a[mi][0]), "r"(a[mi][1]), "r"(a[mi][2]), "r"(a[mi][3]),
                          "r"(b0), "r"(b1));
                }
        }
        st = (st + 1 == 3) ? 0 : st + 1;
        pf = (pf + 1 == 3) ? 0 : pf + 1;
    }

    // ---- epilogue: out[bt, oc, n] = acc + bias[oc]*s[bt,oc] ----
    const int bt_base = col0 / 197;
    const int col197  = (bt_base + 1) * 197;
    int bt1 = bt_base + 1; if (bt1 > 127) bt1 = 127;

    float bvsv[4][2][2];
    #pragma unroll
    for (int mi = 0; mi < 4; mi++)
        #pragma unroll
        for (int h = 0; h < 2; h++) {
            int oc = g * 768 + mt * 128 + wm * 64 + mi * 16 + lr + h * 8;
            float bv = bias[oc];
            bvsv[mi][h][0] = bv * g_s[bt_base * 2304 + oc];
            bvsv[mi][h][1] = bv * g_s[bt1 * 2304 + oc];
        }

    #pragma unroll
    for (int mi = 0; mi < 4; mi++)
        #pragma unroll
        for (int ni = 0; ni < 8; ni++)
            #pragma unroll
            for (int e = 0; e < 4; e++) {
                const int h   = e >> 1;
                const int oc  = g * 768 + mt * 128 + wm * 64 + mi * 16 + lr + h * 8;
                const int col = col0 + wn * 64 + ni * 8 + lc * 2 + (e & 1);
                const int bs  = (col >= col197) ? 1 : 0;
                const float add = bs ? bvsv[mi][h][1] : bvsv[mi][h][0];
                // idx = bt*OUTBT + oc*197 + (col - bt*197) = col + oc*197 + bt*453691
                const size_t idx = (size_t)col + (size_t)oc * 197
                                 + (size_t)(bt_base + bs) * 453691;
                out[idx] = acc[mi][ni][e] + add;
            }
}

extern "C" void kernel_launch(void* const* d_in, const int* in_sizes, int n_in,
                              void* d_out, int out_size)
{
    const float* x    = (const float*)d_in[0];
    const float* aw   = (const float*)d_in[1];
    const float* ab   = (const float*)d_in[2];
    const float* w    = (const float*)d_in[3];
    const float* bias = (const float*)d_in[4];
    float* out = (float*)d_out;

    cudaFuncSetAttribute(tal_main_kernel,
                         cudaFuncAttributeMaxDynamicSharedMemorySize, SMEM_MAIN);

    routing_kernel<<<dim3(16, 9), 256>>>(x, aw, ab);
    prep_w<<<OC3 * 768 / 1024, 256>>>(w);
    prep_xs<<<NCOLS, 192>>>(x);
    tal_main_kernel<<<dim3(18, 197), 128, SMEM_MAIN>>>(bias, out);
}

// round 5
// speedup vs baseline: 1.7591x; 1.0005x over previous
#include <cuda_runtime.h>
#include <cstdint>

// ---------------- problem constants ----------------
#define NTOK  197
#define BTOT  128          // B*T
#define OC3   2304         // 3*C
#define NCOLS 25216        // BTOT*NTOK
#define OUTBT 453888       // OC3*NTOK

// ---------------- device scratch (static globals: allowed) ----------------
__device__ float    g_s[BTOT * OC3];            // routing scales, 1.18 MB
__device__ unsigned g_wt[OC3 * 768];            // tf32(W), 7.1 MB
__device__ unsigned g_xs[3][NCOLS * 768];       // tf32(x*s) per group, 232 MB

// ---------------- helpers ----------------
__device__ __forceinline__ uint32_t smem_u32(const void* p) {
    uint32_t a;
    asm("{ .reg .u64 t; cvta.to.shared.u64 t, %1; cvt.u32.u64 %0, t; }" : "=r"(a) : "l"(p));
    return a;
}
__device__ __forceinline__ unsigned f2tf(float f) {
    unsigned r;
    asm("cvt.rna.tf32.f32 %0, %1;" : "=r"(r) : "f"(f));
    return r;
}
__device__ __forceinline__ void cp_async16(uint32_t dst, const void* src) {
    asm volatile("cp.async.cg.shared.global [%0], [%1], 16;" :: "r"(dst), "l"(src) : "memory");
}
#define CP_COMMIT() asm volatile("cp.async.commit_group;" ::: "memory")
#define CP_WAIT1()  asm volatile("cp.async.wait_group 1;" ::: "memory")

#define LDSM_X4(r0, r1, r2, r3, addr) \
    asm volatile("ldmatrix.sync.aligned.m8n8.x4.shared.b16 {%0,%1,%2,%3}, [%4];" \
        : "=r"(r0), "=r"(r1), "=r"(r2), "=r"(r3) : "r"(addr))

#define SWZ(off) ((off) ^ (((off) >> 3) & 0x70))

// ---------------------------------------------------------------------------
// Routing: r[b,oc,t] = conv1d_k3(cls)[oc,t] + ab[oc] + 1 -> g_s[(b*8+t)*2304+oc]
// One thread per oc handles ALL 8 t (weights read once). grid=(16,9), block 256.
// ---------------------------------------------------------------------------
__global__ __launch_bounds__(256) void routing_kernel(
    const float* __restrict__ x, const float* __restrict__ aw,
    const float* __restrict__ ab)
{
    __shared__ float cls[10][772];   // rows 1..8 = cls(t), 0/9 zero pad
    const int b   = blockIdx.x;
    const int oc  = blockIdx.y * 256 + threadIdx.x;
    const int tid = threadIdx.x;

    #pragma unroll
    for (int tp = 0; tp < 8; tp++)
        for (int ic = tid; ic < 768; ic += 256)
            cls[tp + 1][ic] = x[(size_t)((b * 8 + tp) * 197) * 768 + ic];
    for (int ic = tid; ic < 772; ic += 256) { cls[0][ic] = 0.f; cls[9][ic] = 0.f; }
    __syncthreads();

    const float* wr = aw + (size_t)oc * 2304;   // aw[oc][ic][k]
    float acc[8];
    #pragma unroll
    for (int t = 0; t < 8; t++) acc[t] = 0.f;

    for (int ic = 0; ic < 768; ic += 4) {
        float4 w0 = *(const float4*)(wr + ic * 3);
        float4 w1 = *(const float4*)(wr + ic * 3 + 4);
        float4 w2 = *(const float4*)(wr + ic * 3 + 8);
        float cv[10][4];
        #pragma unroll
        for (int j = 0; j < 10; j++) {
            cv[j][0] = cls[j][ic];     cv[j][1] = cls[j][ic + 1];
            cv[j][2] = cls[j][ic + 2]; cv[j][3] = cls[j][ic + 3];
        }
        #pragma unroll
        for (int t = 0; t < 8; t++) {
            acc[t] += cv[t][0] * w0.x + cv[t+1][0] * w0.y + cv[t+2][0] * w0.z;
            acc[t] += cv[t][1] * w0.w + cv[t+1][1] * w1.x + cv[t+2][1] * w1.y;
            acc[t] += cv[t][2] * w1.z + cv[t+1][2] * w1.w + cv[t+2][2] * w2.x;
            acc[t] += cv[t][3] * w2.y + cv[t+1][3] * w2.z + cv[t+2][3] * w2.w;
        }
    }
    float abv = ab[oc] + 1.0f;
    #pragma unroll
    for (int t = 0; t < 8; t++)
        g_s[(b * 8 + t) * 2304 + oc] = acc[t] + abv;
}

// ---------------------------------------------------------------------------
// Prep: W -> tf32(RNA) ;  x,s -> tf32(x*s) per group
// ---------------------------------------------------------------------------
__global__ __launch_bounds__(256) void prep_w(const float* __restrict__ w)
{
    int i = (blockIdx.x * 256 + threadIdx.x) * 4;
    float4 v = *(const float4*)(w + i);
    uint4 o = { f2tf(v.x), f2tf(v.y), f2tf(v.z), f2tf(v.w) };
    *(uint4*)(g_wt + i) = o;
}

__global__ __launch_bounds__(192) void prep_xs(const float* __restrict__ x)
{
    const int col = blockIdx.x;
    const int k   = threadIdx.x * 4;
    const int bt  = col / 197;
    float4 xv = *(const float4*)(x + (size_t)col * 768 + k);
    #pragma unroll
    for (int g = 0; g < 3; g++) {
        float4 sv = *(const float4*)(g_s + bt * 2304 + g * 768 + k);
        uint4 o = { f2tf(xv.x * sv.x), f2tf(xv.y * sv.y),
                    f2tf(xv.z * sv.z), f2tf(xv.w * sv.w) };
        *(uint4*)(&g_xs[g][(size_t)col * 768 + k]) = o;
    }
}

// ---------------------------------------------------------------------------
// Main GEMM (mma.sync tf32 m16n8k8): per g, out[o,cj] = sum_k Wt[o,k]*Xs[cj,k]
// CTA tile 128x128, BK=32, 3-stage cp.async, software-pipelined ldmatrix frags.
// 4 warps = 2(m) x 2(n): warp tile 64x64. 2 CTAs/SM. grid=(18,197), block 128.
// ---------------------------------------------------------------------------
#define STAGES      3
#define STAGE_BYTES 32768            // A 16K + B 16K
#define SMEM_MAIN   (STAGES * STAGE_BYTES)

__global__ __launch_bounds__(128, 2)
void tal_main_kernel(const float* __restrict__ bias, float* __restrict__ out)
{
    extern __shared__ char smem[];
    const uint32_t sb = smem_u32(smem);

    const int bx   = blockIdx.x;
    const int g    = bx / 6, mt = bx % 6;
    const int col0 = blockIdx.y * 128;
    const int tid  = threadIdx.x;
    const int lane = tid & 31, warp = tid >> 5;
    const int wm = warp & 1, wn = warp >> 1;      // 2x2 warp grid, 64x64 tiles
    const int lr = lane >> 2, lc = lane & 3;

    // ---- cp.async addressing: ONE base each; i strides are constant ----
    // row_i = (tid>>3) + 16*i ; global step 16*768=12288 ; smem step 2048
    // (SW128 XOR touches bits 7-9 only, so +2048 strides commute with SWZ)
    const int r0 = tid >> 3, q4 = (tid & 7) * 4;
    const uint32_t dst0 = SWZ((uint32_t)(r0 * 128 + q4 * 4));
    const unsigned* aptr = g_wt + (size_t)(g * 768 + mt * 128 + r0) * 768 + q4;
    const unsigned* bptr = g_xs[g] + (size_t)(col0 + r0) * 768 + q4;

    // ---- ldmatrix base offsets (ks=0); per-ks addr = base ^ (ks<<5) ----
    const int lrow = lane & 15, qhi = lane >> 4;
    uint32_t aoff[4], boff[4];
    #pragma unroll
    for (int mi = 0; mi < 4; mi++)
        aoff[mi] = SWZ((uint32_t)((wm * 64 + mi * 16 + lrow) * 128 + qhi * 16));
    #pragma unroll
    for (int nj = 0; nj < 4; nj++)
        boff[nj] = SWZ((uint32_t)((wn * 64 + nj * 16 + lrow) * 128 + qhi * 16));

    float acc[4][8][4];
    #pragma unroll
    for (int mi = 0; mi < 4; mi++)
        #pragma unroll
        for (int ni = 0; ni < 8; ni++)
            #pragma unroll
            for (int e = 0; e < 4; e++) acc[mi][ni][e] = 0.f;

    auto COPY = [&](int st, int c) {
        const uint32_t sA = sb + st * STAGE_BYTES;
        const uint32_t sB = sA + 16384;
        const unsigned* ap = aptr + c * 32;
        const unsigned* bp = bptr + c * 32;
        #pragma unroll
        for (int i = 0; i < 8; i++) {
            cp_async16(sA + dst0 + i * 2048, ap + i * 12288);
            cp_async16(sB + dst0 + i * 2048, bp + i * 12288);
        }
    };

    COPY(0, 0); CP_COMMIT();
    COPY(1, 1); CP_COMMIT();

    uint32_t a[2][4][4], b[2][4][4];   // double-buffered fragments

    int st = 0, pf = 2;
    for (int c = 0; c < 24; c++) {
        CP_WAIT1();
        __syncthreads();
        if (c + 2 < 24) COPY(pf, c + 2);
        CP_COMMIT();

        const uint32_t sA = sb + st * STAGE_BYTES;
        const uint32_t sB = sA + 16384;

        // preload ks=0 fragments
        #pragma unroll
        for (int mi = 0; mi < 4; mi++)
            LDSM_X4(a[0][mi][0], a[0][mi][1], a[0][mi][2], a[0][mi][3], sA + aoff[mi]);
        #pragma unroll
        for (int nj = 0; nj < 4; nj++)
            LDSM_X4(b[0][nj][0], b[0][nj][1], b[0][nj][2], b[0][nj][3], sB + boff[nj]);

        #pragma unroll
        for (int ks = 0; ks < 4; ks++) {
            const int cur = ks & 1, nxt = cur ^ 1;
            if (ks < 3) {
                const uint32_t kx = (uint32_t)((ks + 1) << 5);
                #pragma unroll
                for (int mi = 0; mi < 4; mi++)
                    LDSM_X4(a[nxt][mi][0], a[nxt][mi][1], a[nxt][mi][2], a[nxt][mi][3],
                            sA + (aoff[mi] ^ kx));
                #pragma unroll
                for (int nj = 0; nj < 4; nj++)
                    LDSM_X4(b[nxt][nj][0], b[nxt][nj][1], b[nxt][nj][2], b[nxt][nj][3],
                            sB + (boff[nj] ^ kx));
            }
            #pragma unroll
            for (int mi = 0; mi < 4; mi++)
                #pragma unroll
                for (int ni = 0; ni < 8; ni++) {
                    const uint32_t b0 = b[cur][ni >> 1][ni & 1];
                    const uint32_t b1 = b[cur][ni >> 1][(ni & 1) + 2];
                    asm volatile(
                        "mma.sync.aligned.m16n8k8.row.col.f32.tf32.tf32.f32 "
                        "{%0,%1,%2,%3},{%4,%5,%6,%7},{%8,%9},{%0,%1,%2,%3};\n"
                        : "+f"(acc[mi][ni][0]), "+f"(acc[mi][ni][1]),
                          "+f"(acc[mi][ni][2]), "+f"(acc[mi][ni][3])
                        : "r"(a[cur][mi][0]), "r"(a[cur][mi][1]),
                          "r"(a[cur][mi][2]), "r"(a[cur][mi][3]),
                          "r"(b0), "r"(b1));
                }
        }
        st = (st + 1 == 3) ? 0 : st + 1;
        pf = (pf + 1 == 3) ? 0 : pf + 1;
    }

    // ---- epilogue: out[bt, oc, n] = acc + bias[oc]*s[bt,oc] ----
    const int bt_base = col0 / 197;
    const int col197  = (bt_base + 1) * 197;
    int bt1 = bt_base + 1; if (bt1 > 127) bt1 = 127;

    float bvsv[4][2][2];
    #pragma unroll
    for (int mi = 0; mi < 4; mi++)
        #pragma unroll
        for (int h = 0; h < 2; h++) {
            int oc = g * 768 + mt * 128 + wm * 64 + mi * 16 + lr + h * 8;
            float bv = bias[oc];
            bvsv[mi][h][0] = bv * g_s[bt_base * 2304 + oc];
            bvsv[mi][h][1] = bv * g_s[bt1 * 2304 + oc];
        }

    #pragma unroll
    for (int mi = 0; mi < 4; mi++)
        #pragma unroll
        for (int ni = 0; ni < 8; ni++)
            #pragma unroll
            for (int e = 0; e < 4; e++) {
                const int h   = e >> 1;
                const int oc  = g * 768 + mt * 128 + wm * 64 + mi * 16 + lr + h * 8;
                const int col = col0 + wn * 64 + ni * 8 + lc * 2 + (e & 1);
                const int bs  = (col >= col197) ? 1 : 0;
                const float add = bs ? bvsv[mi][h][1] : bvsv[mi][h][0];
                // idx = bt*OUTBT + oc*197 + (col - bt*197) = col + oc*197 + bt*453691
                const size_t idx = (size_t)col + (size_t)oc * 197
                                 + (size_t)(bt_base + bs) * 453691;
                out[idx] = acc[mi][ni][e] + add;
            }
}

extern "C" void kernel_launch(void* const* d_in, const int* in_sizes, int n_in,
                              void* d_out, int out_size)
{
    const float* x    = (const float*)d_in[0];
    const float* aw   = (const float*)d_in[1];
    const float* ab   = (const float*)d_in[2];
    const float* w    = (const float*)d_in[3];
    const float* bias = (const float*)d_in[4];
    float* out = (float*)d_out;

    cudaFuncSetAttribute(tal_main_kernel,
                         cudaFuncAttributeMaxDynamicSharedMemorySize, SMEM_MAIN);

    routing_kernel<<<dim3(16, 9), 256>>>(x, aw, ab);
    prep_w<<<OC3 * 768 / 1024, 256>>>(w);
    prep_xs<<<NCOLS, 192>>>(x);
    tal_main_kernel<<<dim3(18, 197), 128, SMEM_MAIN>>>(bias, out);
}

// round 6
// speedup vs baseline: 2.8245x; 1.6056x over previous
#include <cuda_runtime.h>
#include <cuda_fp16.h>
#include <cstdint>

// ---------------- problem constants ----------------
#define NTOK  197
#define BTOT  128          // B*T
#define OC3   2304         // 3*C
#define NCOLS 25216        // BTOT*NTOK
#define OUTBT 453888       // OC3*NTOK

// ---------------- device scratch (static globals: allowed) ----------------
__device__ float  g_s[BTOT * OC3];              // routing scales, 1.18 MB
__device__ __half g_wth[OC3 * 768];             // fp16(W), 3.5 MB
__device__ __half g_xsh[3][NCOLS * 768];        // fp16(x*s) per group, 116 MB

// ---------------- helpers ----------------
__device__ __forceinline__ uint32_t smem_u32(const void* p) {
    uint32_t a;
    asm("{ .reg .u64 t; cvta.to.shared.u64 t, %1; cvt.u32.u64 %0, t; }" : "=r"(a) : "l"(p));
    return a;
}
__device__ __forceinline__ void cp_async16(uint32_t dst, const void* src) {
    asm volatile("cp.async.cg.shared.global [%0], [%1], 16;" :: "r"(dst), "l"(src) : "memory");
}
#define CP_COMMIT() asm volatile("cp.async.commit_group;" ::: "memory")
#define CP_WAIT1()  asm volatile("cp.async.wait_group 1;" ::: "memory")

#define LDSM_X4(r0, r1, r2, r3, addr) \
    asm volatile("ldmatrix.sync.aligned.m8n8.x4.shared.b16 {%0,%1,%2,%3}, [%4];" \
        : "=r"(r0), "=r"(r1), "=r"(r2), "=r"(r3) : "r"(addr))

#define SWZ(off) ((off) ^ (((off) >> 3) & 0x70))

// ---------------------------------------------------------------------------
// Routing: r[b,oc,t] = conv1d_k3(cls)[oc,t] + ab[oc] + 1 -> g_s[(b*8+t)*2304+oc]
// One thread per oc handles ALL 8 t (weights read once). grid=(16,9), block 256.
// ---------------------------------------------------------------------------
__global__ __launch_bounds__(256) void routing_kernel(
    const float* __restrict__ x, const float* __restrict__ aw,
    const float* __restrict__ ab)
{
    __shared__ float cls[10][772];   // rows 1..8 = cls(t), 0/9 zero pad
    const int b   = blockIdx.x;
    const int oc  = blockIdx.y * 256 + threadIdx.x;
    const int tid = threadIdx.x;

    #pragma unroll
    for (int tp = 0; tp < 8; tp++)
        for (int ic = tid; ic < 768; ic += 256)
            cls[tp + 1][ic] = x[(size_t)((b * 8 + tp) * 197) * 768 + ic];
    for (int ic = tid; ic < 772; ic += 256) { cls[0][ic] = 0.f; cls[9][ic] = 0.f; }
    __syncthreads();

    const float* wr = aw + (size_t)oc * 2304;   // aw[oc][ic][k]
    float acc[8];
    #pragma unroll
    for (int t = 0; t < 8; t++) acc[t] = 0.f;

    for (int ic = 0; ic < 768; ic += 4) {
        float4 w0 = *(const float4*)(wr + ic * 3);
        float4 w1 = *(const float4*)(wr + ic * 3 + 4);
        float4 w2 = *(const float4*)(wr + ic * 3 + 8);
        float cv[10][4];
        #pragma unroll
        for (int j = 0; j < 10; j++) {
            cv[j][0] = cls[j][ic];     cv[j][1] = cls[j][ic + 1];
            cv[j][2] = cls[j][ic + 2]; cv[j][3] = cls[j][ic + 3];
        }
        #pragma unroll
        for (int t = 0; t < 8; t++) {
            acc[t] += cv[t][0] * w0.x + cv[t+1][0] * w0.y + cv[t+2][0] * w0.z;
            acc[t] += cv[t][1] * w0.w + cv[t+1][1] * w1.x + cv[t+2][1] * w1.y;
            acc[t] += cv[t][2] * w1.z + cv[t+1][2] * w1.w + cv[t+2][2] * w2.x;
            acc[t] += cv[t][3] * w2.y + cv[t+1][3] * w2.z + cv[t+2][3] * w2.w;
        }
    }
    float abv = ab[oc] + 1.0f;
    #pragma unroll
    for (int t = 0; t < 8; t++)
        g_s[(b * 8 + t) * 2304 + oc] = acc[t] + abv;
}

// ---------------------------------------------------------------------------
// Prep: W -> fp16(RN) ;  x,s -> fp16(x*s) per group
// ---------------------------------------------------------------------------
__global__ __launch_bounds__(256) void prep_w(const float* __restrict__ w)
{
    int i = (blockIdx.x * 256 + threadIdx.x) * 4;
    float4 v = *(const float4*)(w + i);
    __half2 h0 = __floats2half2_rn(v.x, v.y);
    __half2 h1 = __floats2half2_rn(v.z, v.w);
    uint2 o = { *(uint32_t*)&h0, *(uint32_t*)&h1 };
    *(uint2*)(&g_wth[i]) = o;
}

__global__ __launch_bounds__(192) void prep_xs(const float* __restrict__ x)
{
    const int col = blockIdx.x;
    const int k   = threadIdx.x * 4;
    const int bt  = col / 197;
    float4 xv = *(const float4*)(x + (size_t)col * 768 + k);
    #pragma unroll
    for (int g = 0; g < 3; g++) {
        float4 sv = *(const float4*)(g_s + bt * 2304 + g * 768 + k);
        __half2 h0 = __floats2half2_rn(xv.x * sv.x, xv.y * sv.y);
        __half2 h1 = __floats2half2_rn(xv.z * sv.z, xv.w * sv.w);
        uint2 o = { *(uint32_t*)&h0, *(uint32_t*)&h1 };
        *(uint2*)(&g_xsh[g][(size_t)col * 768 + k]) = o;
    }
}

// ---------------------------------------------------------------------------
// Main GEMM (mma.sync fp16 m16n8k16): per g, out[o,cj] = sum_k Wh[o,k]*Xh[cj,k]
// CTA tile 128x128, BK=64 halfs (128B SW128 rows), 12 chunks, 3-stage cp.async.
// 4 warps = 2(m) x 2(n): warp tile 64x64. 2 CTAs/SM. grid=(18,197), block 128.
// ---------------------------------------------------------------------------
#define STAGES      3
#define STAGE_BYTES 32768            // A 16K + B 16K
#define SMEM_MAIN   (STAGES * STAGE_BYTES)
#define NCHUNK      12

__global__ __launch_bounds__(128, 2)
void tal_main_kernel(const float* __restrict__ bias, float* __restrict__ out)
{
    extern __shared__ char smem[];
    const uint32_t sb = smem_u32(smem);

    const int bx   = blockIdx.x;
    const int g    = bx / 6, mt = bx % 6;
    const int col0 = blockIdx.y * 128;
    const int tid  = threadIdx.x;
    const int lane = tid & 31, warp = tid >> 5;
    const int wm = warp & 1, wn = warp >> 1;      // 2x2 warp grid, 64x64 tiles
    const int lr = lane >> 2, lc = lane & 3;

    // ---- cp.async addressing: one base; constant strides ----
    // row_i = (tid>>3) + 16*i ; global step 16*768 halfs ; smem step 2048 B
    const int r0 = tid >> 3, q8 = (tid & 7) * 8;        // 8 halfs = 16B granule
    const uint32_t dst0 = SWZ((uint32_t)(r0 * 128 + q8 * 2));
    const __half* aptr = g_wth + (size_t)(g * 768 + mt * 128 + r0) * 768 + q8;
    const __half* bptr = g_xsh[g] + (size_t)(col0 + r0) * 768 + q8;

    // ---- ldmatrix base offsets (ks=0); per-ks addr = base ^ (ks*32) ----
    // A (m16xk16): lane l -> row lane&15, byte (lane>>4)*16
    const int alrow = lane & 15, aqhi = lane >> 4;
    // B (n16xk16 -> two n8 b-frags): lane l -> n-row (l&7)|((l&16)>>1), byte ((l>>3)&1)*16
    const int brow = (lane & 7) | ((lane & 16) >> 1), bq = (lane >> 3) & 1;
    uint32_t aoff[4], boff[4];
    #pragma unroll
    for (int mi = 0; mi < 4; mi++)
        aoff[mi] = SWZ((uint32_t)((wm * 64 + mi * 16 + alrow) * 128 + aqhi * 16));
    #pragma unroll
    for (int nj = 0; nj < 4; nj++)
        boff[nj] = SWZ((uint32_t)((wn * 64 + nj * 16 + brow) * 128 + bq * 16));

    float acc[4][8][4];
    #pragma unroll
    for (int mi = 0; mi < 4; mi++)
        #pragma unroll
        for (int ni = 0; ni < 8; ni++)
            #pragma unroll
            for (int e = 0; e < 4; e++) acc[mi][ni][e] = 0.f;

    auto COPY = [&](int st, int c) {
        const uint32_t sA = sb + st * STAGE_BYTES;
        const uint32_t sB = sA + 16384;
        const __half* ap = aptr + c * 64;
        const __half* bp = bptr + c * 64;
        #pragma unroll
        for (int i = 0; i < 8; i++) {
            cp_async16(sA + dst0 + i * 2048, ap + i * 12288);
            cp_async16(sB + dst0 + i * 2048, bp + i * 12288);
        }
    };

    COPY(0, 0); CP_COMMIT();
    COPY(1, 1); CP_COMMIT();

    int st = 0, pf = 2;
    for (int c = 0; c < NCHUNK; c++) {
        CP_WAIT1();
        __syncthreads();
        if (c + 2 < NCHUNK) COPY(pf, c + 2);
        CP_COMMIT();

        const uint32_t sA = sb + st * STAGE_BYTES;
        const uint32_t sB = sA + 16384;

        #pragma unroll
        for (int ks = 0; ks < 4; ks++) {           // k16 steps within 64-half chunk
            const uint32_t kx = (uint32_t)(ks * 32);
            uint32_t a[4][4], b[4][4];
            #pragma unroll
            for (int mi = 0; mi < 4; mi++)
                LDSM_X4(a[mi][0], a[mi][1], a[mi][2], a[mi][3], sA + (aoff[mi] ^ kx));
            #pragma unroll
            for (int nj = 0; nj < 4; nj++)
                LDSM_X4(b[nj][0], b[nj][1], b[nj][2], b[nj][3], sB + (boff[nj] ^ kx));
            #pragma unroll
            for (int mi = 0; mi < 4; mi++)
                #pragma unroll
                for (int ni = 0; ni < 8; ni++) {
                    const uint32_t b0 = b[ni >> 1][(ni & 1) * 2];
                    const uint32_t b1 = b[ni >> 1][(ni & 1) * 2 + 1];
                    asm volatile(
                        "mma.sync.aligned.m16n8k16.row.col.f32.f16.f16.f32 "
                        "{%0,%1,%2,%3},{%4,%5,%6,%7},{%8,%9},{%0,%1,%2,%3};\n"
                        : "+f"(acc[mi][ni][0]), "+f"(acc[mi][ni][1]),
                          "+f"(acc[mi][ni][2]), "+f"(acc[mi][ni][3])
                        : "r"(a[mi][0]), "r"(a[mi][1]), "r"(a[mi][2]), "r"(a[mi][3]),
                          "r"(b0), "r"(b1));
                }
        }
        st = (st + 1 == 3) ? 0 : st + 1;
        pf = (pf + 1 == 3) ? 0 : pf + 1;
    }

    // ---- epilogue: out[bt, oc, n] = acc + bias[oc]*s[bt,oc] ----
    const int bt_base = col0 / 197;
    const int col197  = (bt_base + 1) * 197;
    int bt1 = bt_base + 1; if (bt1 > 127) bt1 = 127;

    float bvsv[4][2][2];
    #pragma unroll
    for (int mi = 0; mi < 4; mi++)
        #pragma unroll
        for (int h = 0; h < 2; h++) {
            int oc = g * 768 + mt * 128 + wm * 64 + mi * 16 + lr + h * 8;
            float bv = bias[oc];
            bvsv[mi][h][0] = bv * g_s[bt_base * 2304 + oc];
            bvsv[mi][h][1] = bv * g_s[bt1 * 2304 + oc];
        }

    #pragma unroll
    for (int mi = 0; mi < 4; mi++)
        #pragma unroll
        for (int ni = 0; ni < 8; ni++)
            #pragma unroll
            for (int e = 0; e < 4; e++) {
                const int h   = e >> 1;
                const int oc  = g * 768 + mt * 128 + wm * 64 + mi * 16 + lr + h * 8;
                const int col = col0 + wn * 64 + ni * 8 + lc * 2 + (e & 1);
                const int bs  = (col >= col197) ? 1 : 0;
                const float add = bs ? bvsv[mi][h][1] : bvsv[mi][h][0];
                // idx = bt*OUTBT + oc*197 + (col - bt*197) = col + oc*197 + bt*453691
                const size_t idx = (size_t)col + (size_t)oc * 197
                                 + (size_t)(bt_base + bs) * 453691;
                out[idx] = acc[mi][ni][e] + add;
            }
}

extern "C" void kernel_launch(void* const* d_in, const int* in_sizes, int n_in,
                              void* d_out, int out_size)
{
    const float* x    = (const float*)d_in[0];
    const float* aw   = (const float*)d_in[1];
    const float* ab   = (const float*)d_in[2];
    const float* w    = (const float*)d_in[3];
    const float* bias = (const float*)d_in[4];
    float* out = (float*)d_out;

    cudaFuncSetAttribute(tal_main_kernel,
                         cudaFuncAttributeMaxDynamicSharedMemorySize, SMEM_MAIN);

    routing_kernel<<<dim3(16, 9), 256>>>(x, aw, ab);
    prep_w<<<OC3 * 768 / 1024, 256>>>(w);
    prep_xs<<<NCOLS, 192>>>(x);
    tal_main_kernel<<<dim3(18, 197), 128, SMEM_MAIN>>>(bias, out);
}